// round 7
// baseline (speedup 1.0000x reference)
#include <cuda_runtime.h>
#include <stdint.h>

// ============================================================
// EGNN layer: fused edge-MLP fold + tf32 mma.sync GEMMs
//   out = [h + segsum(m, dst) | x + segsum(cw * dir/len, dst)]
// edge_index is int32. Coord columns get split-tf32 correction on the
// 32 edge K-rows (the dominant-magnitude inputs).
// ============================================================

#define ND 64
#define ED 32
#define HD 128
#define K1 160   // 2*ND + ED
#define N1 256   // HD (node) + HD (coord)
#define TILE 64
#define ASTRIDE 196  // 160 hi + 32 s_lo + 4 pad

// --- device scratch (static; no allocation) ---
__device__ uint32_t gW1[K1 * N1];     // fused W1 (tf32 bits), [k][n]
__device__ uint32_t gW1lo[ED * HD];   // w_lo residual, edge rows x coord cols
__device__ float    gBias1[N1];       // fused bias
__device__ uint32_t gWn2[HD * ND];    // Wn2 (tf32 bits), [k][n]

__device__ __forceinline__ uint32_t f2t(float x) {
    uint32_t r;
    asm("cvt.rna.tf32.f32 %0, %1;" : "=r"(r) : "f"(x));
    return r;
}
__device__ __forceinline__ float silu_f(float v) {
    return v / (1.0f + __expf(-v));
}

// ------------------------------------------------------------
// Prep: fold We2/be2 into W1 rows 128..159 and bias; tf32-ify.
// Also emit w_lo residuals for edge rows x coord cols.
// ------------------------------------------------------------
__global__ void prep_kernel(const float* __restrict__ Wn1, const float* __restrict__ Wc1,
                            const float* __restrict__ We2, const float* __restrict__ be2,
                            const float* __restrict__ bn1, const float* __restrict__ bc1,
                            const float* __restrict__ Wn2f)
{
    int b = blockIdx.x, n = threadIdx.x;
    if (b < K1) {
        if (n < N1) {
            const float* W = (n < HD) ? Wn1 : Wc1;
            int nn = (n < HD) ? n : n - HD;
            float v;
            if (b < 2 * ND) {
                v = W[b * HD + nn];
            } else {
                int i = b - 2 * ND;
                float s = 0.0f;
                for (int j = 0; j < ED; j++)
                    s += We2[i * ED + j] * W[(2 * ND + j) * HD + nn];
                v = s;
            }
            uint32_t hb = f2t(v);
            gW1[b * N1 + n] = hb;
            if (b >= 2 * ND && n >= HD)
                gW1lo[(b - 2 * ND) * HD + (n - HD)] = f2t(v - __uint_as_float(hb));
        }
    } else if (b == K1) {
        if (n < N1) {
            const float* W = (n < HD) ? Wn1 : Wc1;
            int nn = (n < HD) ? n : n - HD;
            float s = (n < HD) ? bn1[n] : bc1[nn];
            for (int j = 0; j < ED; j++)
                s += be2[j] * W[(2 * ND + j) * HD + nn];
            gBias1[n] = s;
        }
    } else {
        for (int i = n; i < HD * ND; i += 256)
            gWn2[i] = f2t(Wn2f[i]);
    }
}

// ------------------------------------------------------------
// Init: out = [h | x] (atomics accumulate on top)
// ------------------------------------------------------------
__global__ void init_kernel(const float* __restrict__ h, const float* __restrict__ x,
                            float* __restrict__ out, int nh, int nx)
{
    int i = blockIdx.x * 256 + threadIdx.x;
    if (i < nh)            out[i] = h[i];
    else if (i < nh + nx)  out[i] = x[i - nh];
}

// ------------------------------------------------------------
// SMEM layout (bytes):
//   [0, 163840)        sW    : uint32[160*256] swizzled (n ^ ((k&3)<<3))
//   [163840, 180224)   sWlo  : uint32[32*128] swizzled (coord w_lo)
//   [180224, 230400)   union (phase-fenced by bar.sync):
//       A tile  uint32[64*196]  (50176 B)   phases 1-2
//       sHidN   uint32[64*132]  (33792 B)   phases 3-4
//       sM      float [64*68]   (17408 B)   phases 5-6
//   [230400, 231424)   sP    : float[64*4]  coord dot partials (ph 3->5)
//   [231424, 231936)   sSrc int[64], sDst int[64]
// ------------------------------------------------------------
#define SW_OFF    0
#define SWLO_OFF  163840
#define UN_OFF    180224
#define SP_OFF    230400
#define META_OFF  231424
#define SMEM_TOTAL 231936

__global__ void __launch_bounds__(256, 1)
egnn_kernel(const float* __restrict__ h, const float* __restrict__ x,
            const int* __restrict__ ei, const float* __restrict__ ed,
            const float* __restrict__ We1, const float* __restrict__ be1,
            const float* __restrict__ bn2, const float* __restrict__ Wc2,
            float* __restrict__ out, int E, int NN)
{
    extern __shared__ char smem[];
    uint32_t* sW   = (uint32_t*)(smem + SW_OFF);
    uint32_t* sWlo = (uint32_t*)(smem + SWLO_OFF);
    uint32_t* sA   = (uint32_t*)(smem + UN_OFF);
    uint32_t* sHN  = (uint32_t*)(smem + UN_OFF);
    float*    sM   = (float*)   (smem + UN_OFF);
    float*    sP   = (float*)   (smem + SP_OFF);
    int*      sSrc = (int*)     (smem + META_OFF);
    int*      sDst = (int*)     (smem + META_OFF + 256);

    const int tid = threadIdx.x;
    const int w  = tid >> 5;
    const int l  = tid & 31;
    const int lg = l >> 2;   // group row (0..7)
    const int lt = l & 3;    // thread-in-group
    float* outH = out;
    float* outX = out + (size_t)NN * ND;

    // ---- load fused W1 into SMEM (swizzled), uint4 granularity ----
    {
        const uint4* gw4 = (const uint4*)gW1;
        for (int i = tid; i < K1 * (N1 / 4); i += 256) {
            int k  = i >> 6;
            int n4 = (i & 63) << 2;
            uint4 v = gw4[i];
            int cc = n4 ^ ((k & 3) << 3);
            *(uint4*)&sW[k * N1 + cc] = v;
        }
        const uint4* gl4 = (const uint4*)gW1lo;
        for (int i = tid; i < ED * (HD / 4); i += 256) {
            int k  = i >> 5;
            int n4 = (i & 31) << 2;
            uint4 v = gl4[i];
            int cc = n4 ^ ((k & 3) << 3);
            *(uint4*)&sWlo[k * HD + cc] = v;
        }
    }

    // ---- persistent register preloads ----
    uint32_t bw2[16][2];                       // Wn2 B-fragments
    #pragma unroll
    for (int ks = 0; ks < 16; ks++) {
        int kk = ks * 8 + lt;
        int nn = (w << 3) + lg;
        bw2[ks][0] = gWn2[kk * ND + nn];
        bw2[ks][1] = gWn2[(kk + 4) * ND + nn];
    }
    float bias1g[4][2];
    float wc2r[4][2];
    #pragma unroll
    for (int nt = 0; nt < 4; nt++) {
        int col = (w << 5) + (nt << 3) + (lt << 1);
        bias1g[nt][0] = gBias1[col];
        bias1g[nt][1] = gBias1[col + 1];
        wc2r[nt][0] = (w >= 4) ? Wc2[col - HD]     : 0.0f;
        wc2r[nt][1] = (w >= 4) ? Wc2[col - HD + 1] : 0.0f;
    }
    float bn2g0 = bn2[(w << 3) + (lt << 1)];
    float bn2g1 = bn2[(w << 3) + (lt << 1) + 1];

    __syncthreads();

    const int nTiles = (E + TILE - 1) / TILE;
    for (int t = blockIdx.x; t < nTiles; t += gridDim.x) {
        const int base = t * TILE;

        // ================= phase 1: build A tile =================
        {
            int m  = tid >> 2;
            int t4 = tid & 3;
            int e  = base + m;
            uint32_t* Arow = sA + m * ASTRIDE;
            if (e < E) {
                int src = ei[e];
                int dst = ei[E + e];
                if (t4 == 0) { sSrc[m] = src; sDst[m] = dst; }
                float d = ed[e];
                for (int c = t4; c < 40; c += 4) {
                    if (c < 32) {
                        const float4* rowp = (const float4*)(h + (size_t)(c < 16 ? src : dst) * ND);
                        float4 v = rowp[c & 15];
                        int col = c << 2;
                        Arow[col]     = f2t(v.x);
                        Arow[col + 1] = f2t(v.y);
                        Arow[col + 2] = f2t(v.z);
                        Arow[col + 3] = f2t(v.w);
                    } else {
                        int i0 = (c - 32) << 2;
                        #pragma unroll
                        for (int j = 0; j < 4; j++) {
                            int i = i0 + j;
                            float v = d * We1[i] + be1[i];
                            float s = silu_f(v);
                            uint32_t hi = f2t(s);
                            Arow[128 + i] = hi;
                            Arow[160 + i] = f2t(s - __uint_as_float(hi));
                        }
                    }
                }
            } else {
                if (t4 == 0) { sSrc[m] = 0; sDst[m] = -1; }
                for (int c = t4; c < 48; c += 4) {
                    int col = c << 2;
                    Arow[col] = 0; Arow[col + 1] = 0; Arow[col + 2] = 0; Arow[col + 3] = 0;
                }
            }
        }
        __syncthreads();

        // ================= phase 2: GEMM1 (64x256x160 + coord corr) =========
        float c1[4][4][4];
        #pragma unroll
        for (int a = 0; a < 4; a++)
            #pragma unroll
            for (int b = 0; b < 4; b++)
                #pragma unroll
                for (int r = 0; r < 4; r++) c1[a][b][r] = 0.0f;

        const int sw = lt << 3;
        #pragma unroll 2
        for (int ks = 0; ks < 20; ks++) {
            int k0 = ks << 3;
            uint32_t af[4][4];
            #pragma unroll
            for (int mt = 0; mt < 4; mt++) {
                int ba = ((mt << 4) + lg) * ASTRIDE + k0 + lt;
                af[mt][0] = sA[ba];
                af[mt][1] = sA[ba + 8 * ASTRIDE];
                af[mt][2] = sA[ba + 4];
                af[mt][3] = sA[ba + 8 * ASTRIDE + 4];
            }
            uint32_t bf[4][2];
            int kb = (k0 + lt) * N1;
            #pragma unroll
            for (int nt = 0; nt < 4; nt++) {
                int cc = ((w << 5) + (nt << 3) + lg) ^ sw;
                bf[nt][0] = sW[kb + cc];
                bf[nt][1] = sW[kb + 4 * N1 + cc];
            }
            #pragma unroll
            for (int mt = 0; mt < 4; mt++)
                #pragma unroll
                for (int nt = 0; nt < 4; nt++)
                    asm volatile(
                        "mma.sync.aligned.m16n8k8.row.col.f32.tf32.tf32.f32 "
                        "{%0,%1,%2,%3}, {%4,%5,%6,%7}, {%8,%9}, {%0,%1,%2,%3};"
                        : "+f"(c1[mt][nt][0]), "+f"(c1[mt][nt][1]),
                          "+f"(c1[mt][nt][2]), "+f"(c1[mt][nt][3])
                        : "r"(af[mt][0]), "r"(af[mt][1]), "r"(af[mt][2]), "r"(af[mt][3]),
                          "r"(bf[nt][0]), "r"(bf[nt][1]));
        }

        if (w >= 4) {
            // correction 1: s_lo * w_hi  (A cols 160..191, B = sW rows 128..159)
            #pragma unroll
            for (int ks = 0; ks < 4; ks++) {
                int k0a = 160 + (ks << 3);
                int k0b = 128 + (ks << 3);
                uint32_t af[4][4];
                #pragma unroll
                for (int mt = 0; mt < 4; mt++) {
                    int ba = ((mt << 4) + lg) * ASTRIDE + k0a + lt;
                    af[mt][0] = sA[ba];
                    af[mt][1] = sA[ba + 8 * ASTRIDE];
                    af[mt][2] = sA[ba + 4];
                    af[mt][3] = sA[ba + 8 * ASTRIDE + 4];
                }
                uint32_t bf[4][2];
                int kb = (k0b + lt) * N1;
                #pragma unroll
                for (int nt = 0; nt < 4; nt++) {
                    int cc = ((w << 5) + (nt << 3) + lg) ^ sw;
                    bf[nt][0] = sW[kb + cc];
                    bf[nt][1] = sW[kb + 4 * N1 + cc];
                }
                #pragma unroll
                for (int mt = 0; mt < 4; mt++)
                    #pragma unroll
                    for (int nt = 0; nt < 4; nt++)
                        asm volatile(
                            "mma.sync.aligned.m16n8k8.row.col.f32.tf32.tf32.f32 "
                            "{%0,%1,%2,%3}, {%4,%5,%6,%7}, {%8,%9}, {%0,%1,%2,%3};"
                            : "+f"(c1[mt][nt][0]), "+f"(c1[mt][nt][1]),
                              "+f"(c1[mt][nt][2]), "+f"(c1[mt][nt][3])
                            : "r"(af[mt][0]), "r"(af[mt][1]), "r"(af[mt][2]), "r"(af[mt][3]),
                              "r"(bf[nt][0]), "r"(bf[nt][1]));
            }
            // correction 2: s_hi * w_lo  (A cols 128..159, B = sWlo)
            #pragma unroll
            for (int ks = 0; ks < 4; ks++) {
                int k0a = 128 + (ks << 3);
                int k0b = ks << 3;
                uint32_t af[4][4];
                #pragma unroll
                for (int mt = 0; mt < 4; mt++) {
                    int ba = ((mt << 4) + lg) * ASTRIDE + k0a + lt;
                    af[mt][0] = sA[ba];
                    af[mt][1] = sA[ba + 8 * ASTRIDE];
                    af[mt][2] = sA[ba + 4];
                    af[mt][3] = sA[ba + 8 * ASTRIDE + 4];
                }
                uint32_t bf[4][2];
                int kb = (k0b + lt) * HD;
                #pragma unroll
                for (int nt = 0; nt < 4; nt++) {
                    int cc = (((w - 4) << 5) + (nt << 3) + lg) ^ sw;
                    bf[nt][0] = sWlo[kb + cc];
                    bf[nt][1] = sWlo[kb + 4 * HD + cc];
                }
                #pragma unroll
                for (int mt = 0; mt < 4; mt++)
                    #pragma unroll
                    for (int nt = 0; nt < 4; nt++)
                        asm volatile(
                            "mma.sync.aligned.m16n8k8.row.col.f32.tf32.tf32.f32 "
                            "{%0,%1,%2,%3}, {%4,%5,%6,%7}, {%8,%9}, {%0,%1,%2,%3};"
                            : "+f"(c1[mt][nt][0]), "+f"(c1[mt][nt][1]),
                              "+f"(c1[mt][nt][2]), "+f"(c1[mt][nt][3])
                            : "r"(af[mt][0]), "r"(af[mt][1]), "r"(af[mt][2]), "r"(af[mt][3]),
                              "r"(bf[nt][0]), "r"(bf[nt][1]));
            }
        }
        __syncthreads();  // all warps done reading sA

        // ====== phase 3: bias + SiLU; node->sHN(tf32), coord->dot partials ===
        if (w < 4) {
            #pragma unroll
            for (int mt = 0; mt < 4; mt++)
                #pragma unroll
                for (int nt = 0; nt < 4; nt++)
                    #pragma unroll
                    for (int r = 0; r < 4; r++) {
                        int row = (mt << 4) + lg + ((r >= 2) ? 8 : 0);
                        int col = (w << 5) + (nt << 3) + (lt << 1) + (r & 1);
                        float v = silu_f(c1[mt][nt][r] + bias1g[nt][r & 1]);
                        sHN[row * 132 + col] = f2t(v);
                    }
        } else {
            float part[4][2];
            #pragma unroll
            for (int mt = 0; mt < 4; mt++) { part[mt][0] = 0.0f; part[mt][1] = 0.0f; }
            #pragma unroll
            for (int mt = 0; mt < 4; mt++)
                #pragma unroll
                for (int nt = 0; nt < 4; nt++)
                    #pragma unroll
                    for (int r = 0; r < 4; r++) {
                        float v = silu_f(c1[mt][nt][r] + bias1g[nt][r & 1]);
                        part[mt][r >> 1] += v * wc2r[nt][r & 1];
                    }
            #pragma unroll
            for (int mt = 0; mt < 4; mt++)
                #pragma unroll
                for (int rh = 0; rh < 2; rh++) {
                    float p = part[mt][rh];
                    p += __shfl_xor_sync(0xffffffffu, p, 1);
                    p += __shfl_xor_sync(0xffffffffu, p, 2);
                    if (lt == 0) {
                        int row = (mt << 4) + lg + (rh << 3);
                        sP[row * 4 + (w - 4)] = p;
                    }
                }
        }
        __syncthreads();

        // ================= phase 4: GEMM2 (64x64x128, tf32) =================
        float c2[4][4];
        #pragma unroll
        for (int a = 0; a < 4; a++)
            #pragma unroll
            for (int r = 0; r < 4; r++) c2[a][r] = 0.0f;

        #pragma unroll 4
        for (int ks = 0; ks < 16; ks++) {
            int k0 = ks << 3;
            #pragma unroll
            for (int mt = 0; mt < 4; mt++) {
                int ba = ((mt << 4) + lg) * 132 + k0 + lt;
                uint32_t a0 = sHN[ba];
                uint32_t a1 = sHN[ba + 8 * 132];
                uint32_t a2 = sHN[ba + 4];
                uint32_t a3 = sHN[ba + 8 * 132 + 4];
                asm volatile(
                    "mma.sync.aligned.m16n8k8.row.col.f32.tf32.tf32.f32 "
                    "{%0,%1,%2,%3}, {%4,%5,%6,%7}, {%8,%9}, {%0,%1,%2,%3};"
                    : "+f"(c2[mt][0]), "+f"(c2[mt][1]), "+f"(c2[mt][2]), "+f"(c2[mt][3])
                    : "r"(a0), "r"(a1), "r"(a2), "r"(a3),
                      "r"(bw2[ks][0]), "r"(bw2[ks][1]));
            }
        }
        __syncthreads();  // sHN reads done before sM overwrites

        // ================= phase 5: stage m; coord epilogue =================
        #pragma unroll
        for (int mt = 0; mt < 4; mt++)
            #pragma unroll
            for (int r = 0; r < 4; r++) {
                int row = (mt << 4) + lg + ((r >= 2) ? 8 : 0);
                int col = (w << 3) + (lt << 1) + (r & 1);
                sM[row * 68 + col] = c2[mt][r] + ((r & 1) ? bn2g1 : bn2g0);
            }

        if (tid < TILE) {
            int m = tid;
            int dst = sDst[m];
            if (dst >= 0) {
                float cw = sP[m * 4] + sP[m * 4 + 1] + sP[m * 4 + 2] + sP[m * 4 + 3];
                int src = sSrc[m];
                float dx = x[src * 3]     - x[dst * 3];
                float dy = x[src * 3 + 1] - x[dst * 3 + 1];
                float dz = x[src * 3 + 2] - x[dst * 3 + 2];
                float len = sqrtf(dx * dx + dy * dy + dz * dz);
                len = fmaxf(len, 1e-8f);
                float s = cw / len;
                float* xo = outX + (size_t)dst * 3;
                asm volatile("red.global.add.f32 [%0], %1;" :: "l"(xo),     "f"(s * dx) : "memory");
                asm volatile("red.global.add.f32 [%0], %1;" :: "l"(xo + 1), "f"(s * dy) : "memory");
                asm volatile("red.global.add.f32 [%0], %1;" :: "l"(xo + 2), "f"(s * dz) : "memory");
            }
        }
        __syncthreads();  // sM visible to all

        // ================= phase 6: scatter h messages =================
        for (int i = tid; i < TILE * 16; i += 256) {
            int m = i >> 4, q = i & 15;
            int dst = sDst[m];
            if (dst >= 0) {
                float4 v = *(const float4*)(sM + m * 68 + (q << 2));
                float* ho = outH + (size_t)dst * ND + (q << 2);
                asm volatile("red.global.add.v4.f32 [%0], {%1,%2,%3,%4};"
                             :: "l"(ho), "f"(v.x), "f"(v.y), "f"(v.z), "f"(v.w) : "memory");
            }
        }
        __syncthreads();  // sM / sP reads done before next tile
    }
}

// ------------------------------------------------------------
extern "C" void kernel_launch(void* const* d_in, const int* in_sizes, int n_in,
                              void* d_out, int out_size)
{
    const float* h   = (const float*)d_in[0];
    const float* x   = (const float*)d_in[1];
    const int*   ei  = (const int*)d_in[2];      // int32 (JAX x64 disabled)
    const float* ed  = (const float*)d_in[3];
    const float* We1 = (const float*)d_in[4];
    const float* be1 = (const float*)d_in[5];
    const float* We2 = (const float*)d_in[6];
    const float* be2 = (const float*)d_in[7];
    const float* Wn1 = (const float*)d_in[8];
    const float* bn1 = (const float*)d_in[9];
    const float* Wn2 = (const float*)d_in[10];
    const float* bn2 = (const float*)d_in[11];
    const float* Wc1 = (const float*)d_in[12];
    const float* bc1 = (const float*)d_in[13];
    const float* Wc2 = (const float*)d_in[14];
    float* out = (float*)d_out;

    int E  = in_sizes[3];        // edge_dist element count
    int NN = in_sizes[0] / ND;   // nodes

    cudaFuncSetAttribute(egnn_kernel, cudaFuncAttributeMaxDynamicSharedMemorySize, SMEM_TOTAL);

    prep_kernel<<<K1 + 2, 256>>>(Wn1, Wc1, We2, be2, bn1, bc1, Wn2);

    int tot = NN * ND + NN * 3;
    init_kernel<<<(tot + 255) / 256, 256>>>(h, x, out, NN * ND, NN * 3);

    egnn_kernel<<<148, 256, SMEM_TOTAL>>>(h, x, ei, ed, We1, be1, bn2, Wc2, out, E, NN);
}